// round 3
// baseline (speedup 1.0000x reference)
#include <cuda_runtime.h>
#include <math.h>

#define NS 4096
#define NT 4096
#define RPB 8
typedef unsigned long long ull;

__device__ double g_acc = 0.0;
__device__ unsigned int g_cnt = 0;

// ---- f32x2 packed helpers (sm_103a) ----
__device__ __forceinline__ ull pk2(float lo, float hi) {
    ull r; asm("mov.b64 %0,{%1,%2};" : "=l"(r) : "f"(lo), "f"(hi)); return r;
}
__device__ __forceinline__ float2 unpk2(ull v) {
    float2 f; asm("mov.b64 {%0,%1},%2;" : "=f"(f.x), "=f"(f.y) : "l"(v)); return f;
}
__device__ __forceinline__ ull fma2_(ull a, ull b, ull c) {
    ull d; asm("fma.rn.f32x2 %0,%1,%2,%3;" : "=l"(d) : "l"(a), "l"(b), "l"(c)); return d;
}
__device__ __forceinline__ ull add2_(ull a, ull b) {
    ull d; asm("add.rn.f32x2 %0,%1,%2;" : "=l"(d) : "l"(a), "l"(b)); return d;
}
__device__ __forceinline__ ull mul2_(ull a, ull b) {
    ull d; asm("mul.rn.f32x2 %0,%1,%2;" : "=l"(d) : "l"(a), "l"(b)); return d;
}

__global__ __launch_bounds__(256) void loss_kernel(const float* __restrict__ V,
                                                   float C1, float dL,
                                                   float* __restrict__ out,
                                                   unsigned int nblocks)
{
    __shared__ ulonglong2 scA[RPB];   // {a2, -b2}
    __shared__ ulonglong2 scB[RPB];   // {-c2_2, -c1_2}
    __shared__ double ws[8];

    const int tid  = threadIdx.x;
    const int lane = tid & 31;
    const int bx   = blockIdx.x;
    const int by   = blockIdx.y;
    const int j0   = bx * 1024 + tid * 4;
    const int r_begin = by * RPB;

    const float INV2DT = 4095.0f / 0.04f;   // (N_T-1)/(2*TAU_MAX)
    const float INV2DU = 4095.0f * 0.5f;
    const float INVDU2 = 4095.0f * 4095.0f;

    // per-row stretched-grid coefficients (broadcast via smem)
    if (tid < RPB) {
        int i = r_begin + tid;
        float u   = (float)i * (1.0f / 4095.0f);
        float L   = fmaf(dL, u, C1);
        float L2  = L * L;
        float S   = fmaf(30.0f, fmaf(L2 * L, (1.0f / 6.0f), L), 100.0f);
        float Sn  = S * (1.0f / 300.0f);
        float Su  = 0.1f * dL * fmaf(0.5f, L2, 1.0f);
        float Suu = 0.1f * dL * dL * L;
        float rSu  = 1.0f / Su;
        float rSu2 = rSu * rSu;
        float a  = INVDU2 * rSu2;
        float b  = INV2DU * Suu * rSu2 * rSu;
        float c2 = Sn * Sn;
        float c1 = 2.5f * Sn * INV2DU * rSu;
        scA[tid] = make_ulonglong2(pk2(a, a),     pk2(-b, -b));
        scB[tid] = make_ulonglong2(pk2(-c2, -c2), pk2(-c1, -c1));
    }
    __syncthreads();

    const int i_lo = (r_begin < 1) ? 1 : r_begin;
    const int i_hi_raw = r_begin + RPB - 1;
    const int i_hi = (i_hi_raw > NS - 2) ? (NS - 2) : i_hi_raw;

    const float w_first = (j0 == 0)          ? 0.0f : 1.0f;
    const float w_last  = (j0 + 3 == NT - 1) ? 0.0f : 1.0f;

    const ull NEG1 = pk2(-1.0f, -1.0f);
    const ull M2   = pk2(-2.0f, -2.0f);
    const ull C252 = pk2(2.5f, 2.5f);
    const ull IDT2 = pk2(INV2DT, INV2DT);
    const ull W01  = pk2(w_first, 1.0f);
    const ull W23  = pk2(1.0f, w_last);

    // edge-scalar column offsets (clamped)
    const int jL = (j0 > 0) ? j0 - 1 : 0;
    const int jR = (j0 + 4 < NT) ? j0 + 4 : NT - 1;
    const bool isL = (lane == 0);
    const bool isR = (lane == 31);

    // ---- software pipeline: window rows i-1, i, i+1 with prefetch of i+2 ----
    const float* base = V + j0;
    float4 vm4 = *(const float4*)(base + (size_t)(i_lo - 1) * NT);
    float4 vc4 = *(const float4*)(base + (size_t)i_lo       * NT);
    float4 vp4 = *(const float4*)(base + (size_t)(i_lo + 1) * NT);

    // edge scalars for the first center row (i_lo)
    float eL = 0.0f, eR = 0.0f;
    if (isL) eL = __ldg(V + (size_t)i_lo * NT + jL);
    if (isR) eR = __ldg(V + (size_t)i_lo * NT + jR);

    ull um01 = pk2(vm4.x, vm4.y), um23 = pk2(vm4.z, vm4.w);
    ull cc01 = pk2(vc4.x, vc4.y), cc23 = pk2(vc4.z, vc4.w);
    ull acc0 = 0ull, acc1 = 0ull;

    #pragma unroll 2
    for (int i = i_lo; i <= i_hi; ++i) {
        // prefetch row i+2 (clamped to NS-1) and next center's edge scalars
        int inext = (i + 2 <= NS - 1) ? i + 2 : NS - 1;
        float4 vn4 = *(const float4*)(base + (size_t)inext * NT);
        float eLn = 0.0f, eRn = 0.0f;
        if (isL) eLn = __ldg(V + (size_t)(i + 1) * NT + jL);
        if (isR) eRn = __ldg(V + (size_t)(i + 1) * NT + jR);

        float left  = __shfl_up_sync(0xffffffffu, vc4.w, 1);
        float right = __shfl_down_sync(0xffffffffu, vc4.x, 1);
        if (isL) left  = eL;
        if (isR) right = eR;

        ull up01 = pk2(vp4.x, vp4.y), up23 = pk2(vp4.z, vp4.w);
        ull cL01 = pk2(left, vc4.x);
        ull yz   = pk2(vc4.y, vc4.z);          // shared: cL23 == cR01
        ull cR23 = pk2(vc4.w, right);

        ulonglong2 cA = scA[i - r_begin];
        ulonglong2 cB = scB[i - r_begin];

        ull Du01  = fma2_(um01, NEG1, up01);
        ull Du23  = fma2_(um23, NEG1, up23);
        ull Duu01 = fma2_(cc01, M2, add2_(up01, um01));
        ull Duu23 = fma2_(cc23, M2, add2_(up23, um23));

        ull VSS01 = fma2_(Duu01, cA.x, mul2_(Du01, cA.y));
        ull VSS23 = fma2_(Duu23, cA.x, mul2_(Du23, cA.y));
        float2 t0 = unpk2(VSS01);
        t0.x = fminf(fmaxf(t0.x, -100.0f), 100.0f);
        t0.y = fminf(fmaxf(t0.y, -100.0f), 100.0f);
        VSS01 = pk2(t0.x, t0.y);
        float2 t1 = unpk2(VSS23);
        t1.x = fminf(fmaxf(t1.x, -100.0f), 100.0f);
        t1.y = fminf(fmaxf(t1.y, -100.0f), 100.0f);
        VSS23 = pk2(t1.x, t1.y);

        ull Dt01 = fma2_(cL01, NEG1, yz);
        ull Dt23 = fma2_(yz, NEG1, cR23);

        ull r01 = fma2_(Dt01, IDT2, mul2_(cc01, C252));
        r01 = fma2_(VSS01, cB.x, r01);
        r01 = fma2_(Du01,  cB.y, r01);
        ull r23 = fma2_(Dt23, IDT2, mul2_(cc23, C252));
        r23 = fma2_(VSS23, cB.x, r23);
        r23 = fma2_(Du23,  cB.y, r23);

        acc0 = fma2_(mul2_(r01, W01), r01, acc0);
        acc1 = fma2_(mul2_(r23, W23), r23, acc1);

        // shift window
        um01 = cc01; um23 = cc23;
        cc01 = up01; cc23 = up23;
        vc4 = vp4; vp4 = vn4;
        eL = eLn;  eR = eRn;
    }

    float2 a0 = unpk2(acc0), a1 = unpk2(acc1);
    double p = ((double)a0.x + (double)a0.y + (double)a1.x + (double)a1.y)
             * (1.0 / (4094.0 * 4094.0));

    // ---- BC / TC tails folded into two blocks ----
    if (by == 0 && bx == 0) {
        const float* rowp = V + (size_t)(NS - 1) * NT;
        double s = 0.0;
        for (int t = tid; t < NT; t += 256) {
            float tn = (float)t * (1.0f / 4095.0f);
            float target = 1.0f - (1.0f / 3.0f) * expf(-0.05f * (1.0f - tn));
            float d = rowp[t] - target;
            s += (double)(d * d);
        }
        p += s * (10.0 / (double)NT);
    } else if (by == 0 && bx == 1) {
        double s = 0.0;
        for (int si = tid; si < NS; si += 256) {
            float u  = (float)si * (1.0f / 4095.0f);
            float x  = 50.0f * (u - (1.0f / 3.0f));
            float sp = (fmaxf(x, 0.0f) + log1pf(expf(-fabsf(x)))) * (1.0f / 50.0f);
            float d  = V[(size_t)si * NT + (NT - 1)] - sp;
            float ad = fabsf(d);
            float h  = (ad < 0.01f) ? 0.5f * d * d : 0.01f * (ad - 0.005f);
            s += (double)h;
        }
        p += s * (10.0 / (double)NS);
    }

    // ---- block reduce (double) ----
    #pragma unroll
    for (int o = 16; o > 0; o >>= 1)
        p += __shfl_down_sync(0xffffffffu, p, o);
    if (lane == 0) ws[tid >> 5] = p;
    __syncthreads();

    if (tid == 0) {
        double s = 0.0;
        #pragma unroll
        for (int k = 0; k < 8; ++k) s += ws[k];
        atomicAdd(&g_acc, s);
        __threadfence();
        unsigned int t = atomicAdd(&g_cnt, 1u);
        if (t == nblocks - 1u) {
            double total = atomicAdd(&g_acc, 0.0);
            out[0] = (float)total;
            g_acc = 0.0;
            __threadfence();
            g_cnt = 0u;
        }
    }
}

// Host-side: hyperbolic root of depressed cubic (CubicStretching)
static double solve_depressed_cubic(double Q)
{
    const double p = 6.0;
    const double q = 6.0 * Q;
    double sp = sqrt(p);
    double arg = fabs(q) / (2.0 * p * sp / (3.0 * sqrt(3.0)));
    if (arg < 1.0) arg = 1.0;
    double c = 2.0 * sp * cosh(acosh(arg) / 3.0);
    return (q >= 0.0) ? -c : c;
}

extern "C" void kernel_launch(void* const* d_in, const int* in_sizes, int n_in,
                              void* d_out, int out_size)
{
    const float* V = (const float*)d_in[0];
    float* out = (float*)d_out;

    const double C1 = solve_depressed_cubic((100.0 - 0.0)   / 30.0);
    const double C2 = solve_depressed_cubic((100.0 - 300.0) / 30.0);
    const float C1f = (float)C1;
    const float dLf = (float)(C2 - C1);

    dim3 grid(NT / 1024, NS / RPB);   // (4, 512) = 2048 blocks
    loss_kernel<<<grid, 256>>>(V, C1f, dLf, out, 2048u);
}

// round 4
// speedup vs baseline: 1.5444x; 1.5444x over previous
#include <cuda_runtime.h>
#include <math.h>

#define NS 4096
#define NT 4096
#define RPB 16
typedef unsigned long long ull;

__device__ double g_acc = 0.0;
__device__ unsigned int g_cnt = 0;

// ---- f32x2 packed helpers (sm_103a) ----
__device__ __forceinline__ ull pk2(float lo, float hi) {
    ull r; asm("mov.b64 %0,{%1,%2};" : "=l"(r) : "f"(lo), "f"(hi)); return r;
}
__device__ __forceinline__ float2 unpk2(ull v) {
    float2 f; asm("mov.b64 {%0,%1},%2;" : "=f"(f.x), "=f"(f.y) : "l"(v)); return f;
}
__device__ __forceinline__ ull fma2_(ull a, ull b, ull c) {
    ull d; asm("fma.rn.f32x2 %0,%1,%2,%3;" : "=l"(d) : "l"(a), "l"(b), "l"(c)); return d;
}
__device__ __forceinline__ ull add2_(ull a, ull b) {
    ull d; asm("add.rn.f32x2 %0,%1,%2;" : "=l"(d) : "l"(a), "l"(b)); return d;
}
__device__ __forceinline__ ull mul2_(ull a, ull b) {
    ull d; asm("mul.rn.f32x2 %0,%1,%2;" : "=l"(d) : "l"(a), "l"(b)); return d;
}
__device__ __forceinline__ ull clamp2_(ull v) {
    float2 f = unpk2(v);
    f.x = fminf(fmaxf(f.x, -100.0f), 100.0f);
    f.y = fminf(fmaxf(f.y, -100.0f), 100.0f);
    return pk2(f.x, f.y);
}

__global__ __launch_bounds__(256) void loss_kernel(const float* __restrict__ V,
                                                   float C1, float dL,
                                                   float* __restrict__ out,
                                                   unsigned int nblocks)
{
    __shared__ ulonglong2 scA[RPB];   // {a2, -b2}
    __shared__ ulonglong2 scB[RPB];   // {-c2_2, -c1_2}
    __shared__ double ws[8];

    const int tid  = threadIdx.x;
    const int lane = tid & 31;
    const int bx   = blockIdx.x;
    const int by   = blockIdx.y;
    const int j0   = bx * 2048 + tid * 8;   // 8-column chunk per thread
    const int r_begin = by * RPB;

    const float INV2DT = 4095.0f / 0.04f;   // (N_T-1)/(2*TAU_MAX)
    const float INV2DU = 4095.0f * 0.5f;
    const float INVDU2 = 4095.0f * 4095.0f;

    // per-row stretched-grid coefficients (broadcast via smem)
    if (tid < RPB) {
        int i = r_begin + tid;
        float u   = (float)i * (1.0f / 4095.0f);
        float L   = fmaf(dL, u, C1);
        float L2  = L * L;
        float S   = fmaf(30.0f, fmaf(L2 * L, (1.0f / 6.0f), L), 100.0f);
        float Sn  = S * (1.0f / 300.0f);
        float Su  = 0.1f * dL * fmaf(0.5f, L2, 1.0f);
        float Suu = 0.1f * dL * dL * L;
        float rSu  = 1.0f / Su;
        float rSu2 = rSu * rSu;
        float a  = INVDU2 * rSu2;
        float b  = INV2DU * Suu * rSu2 * rSu;
        float c2 = Sn * Sn;
        float c1 = 2.5f * Sn * INV2DU * rSu;
        scA[tid] = make_ulonglong2(pk2(a, a),     pk2(-b, -b));
        scB[tid] = make_ulonglong2(pk2(-c2, -c2), pk2(-c1, -c1));
    }
    __syncthreads();

    const int i_lo = (r_begin < 1) ? 1 : r_begin;
    const int i_hi_raw = r_begin + RPB - 1;
    const int i_hi = (i_hi_raw > NS - 2) ? (NS - 2) : i_hi_raw;

    const float w_first = (j0 == 0)          ? 0.0f : 1.0f;
    const float w_last  = (j0 + 7 == NT - 1) ? 0.0f : 1.0f;

    const ull NEG1 = pk2(-1.0f, -1.0f);
    const ull M2   = pk2(-2.0f, -2.0f);
    const ull C252 = pk2(2.5f, 2.5f);
    const ull IDT2 = pk2(INV2DT, INV2DT);
    const ull W0   = pk2(w_first, 1.0f);
    const ull W3   = pk2(1.0f, w_last);

    const int jL = (j0 > 0) ? j0 - 1 : 0;
    const int jR = (j0 + 8 < NT) ? j0 + 8 : NT - 1;
    const bool isL = (lane == 0);
    const bool isR = (lane == 31);

    const float* base = V + j0;

    // rolling window: previous row packed, center row as raw floats
    float4 ma = *(const float4*)(base + (size_t)(i_lo - 1) * NT);
    float4 mb = *(const float4*)(base + (size_t)(i_lo - 1) * NT + 4);
    float4 ca = *(const float4*)(base + (size_t)i_lo * NT);
    float4 cb = *(const float4*)(base + (size_t)i_lo * NT + 4);

    ull um0 = pk2(ma.x, ma.y), um1 = pk2(ma.z, ma.w);
    ull um2 = pk2(mb.x, mb.y), um3 = pk2(mb.z, mb.w);
    ull accA = 0ull, accB = 0ull;

    #pragma unroll 2
    for (int i = i_lo; i <= i_hi; ++i) {
        float4 na = *(const float4*)(base + (size_t)(i + 1) * NT);
        float4 nb = *(const float4*)(base + (size_t)(i + 1) * NT + 4);

        float left  = __shfl_up_sync(0xffffffffu, cb.w, 1);
        float right = __shfl_down_sync(0xffffffffu, ca.x, 1);
        if (isL) left  = __ldg(V + (size_t)i * NT + jL);
        if (isR) right = __ldg(V + (size_t)i * NT + jR);

        ull cc0 = pk2(ca.x, ca.y), cc1 = pk2(ca.z, ca.w);
        ull cc2 = pk2(cb.x, cb.y), cc3 = pk2(cb.z, cb.w);
        ull up0 = pk2(na.x, na.y), up1 = pk2(na.z, na.w);
        ull up2 = pk2(nb.x, nb.y), up3 = pk2(nb.z, nb.w);

        // shifted center pairs for the t-stencil
        ull cL0 = pk2(left, ca.x);
        ull s1  = pk2(ca.y, ca.z);
        ull s2  = pk2(ca.w, cb.x);
        ull s3  = pk2(cb.y, cb.z);
        ull cR3 = pk2(cb.w, right);

        ulonglong2 cA = scA[i - r_begin];
        ulonglong2 cB = scB[i - r_begin];

        // pair 0
        {
            ull Du  = fma2_(um0, NEG1, up0);
            ull Duu = fma2_(cc0, M2, add2_(up0, um0));
            ull VSS = clamp2_(fma2_(Duu, cA.x, mul2_(Du, cA.y)));
            ull Dt  = fma2_(cL0, NEG1, s1);
            ull r = fma2_(Dt, IDT2, mul2_(cc0, C252));
            r = fma2_(VSS, cB.x, r);
            r = fma2_(Du,  cB.y, r);
            accA = fma2_(mul2_(r, W0), r, accA);
        }
        // pair 1
        {
            ull Du  = fma2_(um1, NEG1, up1);
            ull Duu = fma2_(cc1, M2, add2_(up1, um1));
            ull VSS = clamp2_(fma2_(Duu, cA.x, mul2_(Du, cA.y)));
            ull Dt  = fma2_(s1, NEG1, s2);
            ull r = fma2_(Dt, IDT2, mul2_(cc1, C252));
            r = fma2_(VSS, cB.x, r);
            r = fma2_(Du,  cB.y, r);
            accB = fma2_(r, r, accB);
        }
        // pair 2
        {
            ull Du  = fma2_(um2, NEG1, up2);
            ull Duu = fma2_(cc2, M2, add2_(up2, um2));
            ull VSS = clamp2_(fma2_(Duu, cA.x, mul2_(Du, cA.y)));
            ull Dt  = fma2_(s2, NEG1, s3);
            ull r = fma2_(Dt, IDT2, mul2_(cc2, C252));
            r = fma2_(VSS, cB.x, r);
            r = fma2_(Du,  cB.y, r);
            accA = fma2_(r, r, accA);
        }
        // pair 3
        {
            ull Du  = fma2_(um3, NEG1, up3);
            ull Duu = fma2_(cc3, M2, add2_(up3, um3));
            ull VSS = clamp2_(fma2_(Duu, cA.x, mul2_(Du, cA.y)));
            ull Dt  = fma2_(s3, NEG1, cR3);
            ull r = fma2_(Dt, IDT2, mul2_(cc3, C252));
            r = fma2_(VSS, cB.x, r);
            r = fma2_(Du,  cB.y, r);
            accB = fma2_(mul2_(r, W3), r, accB);
        }

        // shift window
        um0 = cc0; um1 = cc1; um2 = cc2; um3 = cc3;
        ca = na; cb = nb;
    }

    float2 a0 = unpk2(accA), a1 = unpk2(accB);
    double p = ((double)a0.x + (double)a0.y + (double)a1.x + (double)a1.y)
             * (1.0 / (4094.0 * 4094.0));

    // ---- BC / TC tails folded into two blocks ----
    if (by == 0 && bx == 0) {
        const float* rowp = V + (size_t)(NS - 1) * NT;
        double s = 0.0;
        for (int t = tid; t < NT; t += 256) {
            float tn = (float)t * (1.0f / 4095.0f);
            float target = 1.0f - (1.0f / 3.0f) * expf(-0.05f * (1.0f - tn));
            float d = rowp[t] - target;
            s += (double)(d * d);
        }
        p += s * (10.0 / (double)NT);
    } else if (by == 0 && bx == 1) {
        double s = 0.0;
        for (int si = tid; si < NS; si += 256) {
            float u  = (float)si * (1.0f / 4095.0f);
            float x  = 50.0f * (u - (1.0f / 3.0f));
            float sp = (fmaxf(x, 0.0f) + log1pf(expf(-fabsf(x)))) * (1.0f / 50.0f);
            float d  = V[(size_t)si * NT + (NT - 1)] - sp;
            float ad = fabsf(d);
            float h  = (ad < 0.01f) ? 0.5f * d * d : 0.01f * (ad - 0.005f);
            s += (double)h;
        }
        p += s * (10.0 / (double)NS);
    }

    // ---- block reduce (double) ----
    #pragma unroll
    for (int o = 16; o > 0; o >>= 1)
        p += __shfl_down_sync(0xffffffffu, p, o);
    if (lane == 0) ws[tid >> 5] = p;
    __syncthreads();

    if (tid == 0) {
        double s = 0.0;
        #pragma unroll
        for (int k = 0; k < 8; ++k) s += ws[k];
        atomicAdd(&g_acc, s);
        __threadfence();
        unsigned int t = atomicAdd(&g_cnt, 1u);
        if (t == nblocks - 1u) {
            double total = atomicAdd(&g_acc, 0.0);
            out[0] = (float)total;
            g_acc = 0.0;
            __threadfence();
            g_cnt = 0u;
        }
    }
}

// Host-side: hyperbolic root of depressed cubic (CubicStretching)
static double solve_depressed_cubic(double Q)
{
    const double p = 6.0;
    const double q = 6.0 * Q;
    double sp = sqrt(p);
    double arg = fabs(q) / (2.0 * p * sp / (3.0 * sqrt(3.0)));
    if (arg < 1.0) arg = 1.0;
    double c = 2.0 * sp * cosh(acosh(arg) / 3.0);
    return (q >= 0.0) ? -c : c;
}

extern "C" void kernel_launch(void* const* d_in, const int* in_sizes, int n_in,
                              void* d_out, int out_size)
{
    const float* V = (const float*)d_in[0];
    float* out = (float*)d_out;

    const double C1 = solve_depressed_cubic((100.0 - 0.0)   / 30.0);
    const double C2 = solve_depressed_cubic((100.0 - 300.0) / 30.0);
    const float C1f = (float)C1;
    const float dLf = (float)(C2 - C1);

    dim3 grid(NT / 2048, NS / RPB);   // (2, 256) = 512 blocks
    loss_kernel<<<grid, 256>>>(V, C1f, dLf, out, 512u);
}